// round 5
// baseline (speedup 1.0000x reference)
#include <cuda_runtime.h>
#include <cuda_bf16.h>

// Problem shapes (fixed by the dataset)
#define BB   16384
#define CC   10
#define KK   8
#define DIM  128

#define WARPS_PER_BLOCK 8
#define NBLK (BB / WARPS_PER_BLOCK)   // 2048

// Scratch (device globals: allocation-guard-safe)
__device__ float        g_part[NBLK];
__device__ unsigned int g_cnt = 0;     // self-resetting via atomicInc wrap

// One kernel: warp-per-example gather/dot/BCE, block partial sum,
// then the LAST block to finish folds the 2048 partials into the scalar.
__global__ void __launch_bounds__(32 * WARPS_PER_BLOCK, 1) cbow_main(
    const int*   __restrict__ contexts,   // [B, C]
    const int*   __restrict__ focus,      // [B, K]
    const float* __restrict__ wmask,      // [B, K]
    const float* __restrict__ labels,     // [B, K]
    const float* __restrict__ ctx_emb,    // [VOCAB, DIM]
    const float* __restrict__ neg_emb,    // [VOCAB, DIM]
    float*       __restrict__ out)
{
    const int lane = threadIdx.x & 31;
    const int wid  = threadIdx.x >> 5;
    const int b    = blockIdx.x * WARPS_PER_BLOCK + wid;

    __shared__ float s_row[WARPS_PER_BLOCK];
    __shared__ bool  s_last;

    // Per-lane index/label staging (lanes < C / < K own one entry each)
    int   ctx_i = (lane < CC) ? contexts[b * CC + lane] : 0;
    int   foc_i = (lane < KK) ? focus[b * KK + lane]    : 0;
    float w     = (lane < KK) ? wmask [b * KK + lane]   : 0.0f;
    float y     = (lane < KK) ? labels[b * KK + lane]   : 0.0f;

    // ---- Issue ALL 18 row loads first, into distinct registers (MLP=18) ----
    float4 cv[CC];
#pragma unroll
    for (int c = 0; c < CC; ++c) {
        int row = __shfl_sync(0xffffffffu, ctx_i, c);
        cv[c] = __ldg((const float4*)&ctx_emb[(size_t)row * DIM + lane * 4]);
    }
    float4 tv[KK];
#pragma unroll
    for (int k = 0; k < KK; ++k) {
        int row = __shfl_sync(0xffffffffu, foc_i, k);
        tv[k] = __ldg((const float4*)&neg_emb[(size_t)row * DIM + lane * 4]);
    }

    // ---- Sum-pool context embedding ----
    float4 src = cv[0];
#pragma unroll
    for (int c = 1; c < CC; ++c) {
        src.x += cv[c].x; src.y += cv[c].y; src.z += cv[c].z; src.w += cv[c].w;
    }

    // ---- K dot products; butterfly reduce (independent shuffle chains) ----
    float pred_mine = 0.0f;
#pragma unroll
    for (int k = 0; k < KK; ++k) {
        float d = src.x * tv[k].x + src.y * tv[k].y
                + src.z * tv[k].z + src.w * tv[k].w;
        d += __shfl_xor_sync(0xffffffffu, d, 16);
        d += __shfl_xor_sync(0xffffffffu, d, 8);
        d += __shfl_xor_sync(0xffffffffu, d, 4);
        d += __shfl_xor_sync(0xffffffffu, d, 2);
        d += __shfl_xor_sync(0xffffffffu, d, 1);
        if (lane == k) pred_mine = d;
    }

    // Lane k (< K) computes its weighted BCE term once
    float bce = 0.0f;
    if (lane < KK) {
        // logaddexp(0, x) = max(x,0) + log1p(exp(-|x|))  (stable softplus)
        float sp = fmaxf(pred_mine, 0.0f) + log1pf(expf(-fabsf(pred_mine)));
        bce = w * (sp - pred_mine * y);
    }

    // num = sum_k bce, den = sum_k w  (w is 0 on lanes >= K)
    float num = bce, den = w;
#pragma unroll
    for (int o = 16; o > 0; o >>= 1) {
        num += __shfl_xor_sync(0xffffffffu, num, o);
        den += __shfl_xor_sync(0xffffffffu, den, o);
    }

    // Per-warp row loss -> block partial
    if (lane == 0) s_row[wid] = num / den;
    __syncthreads();
    if (threadIdx.x == 0) {
        float acc = 0.0f;
#pragma unroll
        for (int i = 0; i < WARPS_PER_BLOCK; ++i) acc += s_row[i];
        g_part[blockIdx.x] = acc;
        __threadfence();
        // atomicInc wraps to 0 after NBLK-1 => self-resetting across replays
        unsigned int prev = atomicInc(&g_cnt, NBLK - 1);
        s_last = (prev == NBLK - 1);
    }
    __syncthreads();

    // ---- Last-finishing block folds 2048 partials -> scalar mean ----
    if (s_last) {
        __threadfence();  // acquire: make all g_part writes visible
        const int tid = threadIdx.x;
        // 256 threads x 8 elements, fixed order => deterministic
        float acc = 0.0f;
#pragma unroll
        for (int i = 0; i < NBLK / 256; ++i)
            acc += g_part[tid + i * 256];

        double v = (double)acc;
#pragma unroll
        for (int o = 16; o > 0; o >>= 1)
            v += __shfl_xor_sync(0xffffffffu, v, o);

        __shared__ double s_acc[WARPS_PER_BLOCK];
        if (lane == 0) s_acc[wid] = v;
        __syncthreads();
        if (tid == 0) {
            double t = 0.0;
#pragma unroll
            for (int i = 0; i < WARPS_PER_BLOCK; ++i) t += s_acc[i];
            out[0] = (float)(t / (double)BB);
        }
    }
}

extern "C" void kernel_launch(void* const* d_in, const int* in_sizes, int n_in,
                              void* d_out, int out_size)
{
    const int*   contexts = (const int*)  d_in[0];   // [B, C] int32
    const int*   focus    = (const int*)  d_in[1];   // [B, K] int32
    const float* wmask    = (const float*)d_in[2];   // [B, K] f32
    const float* labels   = (const float*)d_in[3];   // [B, K] f32
    const float* ctx_emb  = (const float*)d_in[4];   // [VOCAB, DIM] f32
    const float* neg_emb  = (const float*)d_in[5];   // [VOCAB, DIM] f32
    float* out = (float*)d_out;

    cbow_main<<<NBLK, 32 * WARPS_PER_BLOCK>>>(
        contexts, focus, wmask, labels, ctx_emb, neg_emb, out);
}

// round 7
// speedup vs baseline: 1.2503x; 1.2503x over previous
#include <cuda_runtime.h>
#include <cuda_bf16.h>

// Problem shapes (fixed by the dataset)
#define BB   16384
#define CC   10
#define KK   8
#define DIM  128
#define NROW (CC + KK)        // 18 rows staged per example

#define WPB   4               // warps (=examples) per block
#define NBLK  (BB / WPB)      // 4096
#define NP2   32

// Scratch (device globals: allocation-guard-safe)
__device__ float  g_part[NBLK];
__device__ double g_p2[NP2];

__device__ __forceinline__ void cp16(void* s, const void* g) {
    unsigned sa = (unsigned)__cvta_generic_to_shared(s);
    asm volatile("cp.async.cg.shared.global [%0], [%1], 16;\n"
                 :: "r"(sa), "l"(g));
}

// Stage 1: one WARP per example. All 18 row fetches go through cp.async
// (LDGSTS) into smem -> hypothesis: not subject to the per-SM outstanding-
// LDG-line cap that flat-lined LDG variants at ~4.5 TB/s regardless of
// MLP (R4: 18) and occupancy (R3: 86%).
__global__ void __launch_bounds__(32 * WPB) cbow_main(
    const int*   __restrict__ contexts,   // [B, C]
    const int*   __restrict__ focus,      // [B, K]
    const float* __restrict__ wmask,      // [B, K]
    const float* __restrict__ labels,     // [B, K]
    const float* __restrict__ ctx_emb,    // [VOCAB, DIM]
    const float* __restrict__ neg_emb)    // [VOCAB, DIM]
{
    __shared__ __align__(16) char sbuf[WPB][NROW][DIM * 4];  // 36 KB
    __shared__ float s_row[WPB];

    const int lane = threadIdx.x & 31;
    const int wid  = threadIdx.x >> 5;
    const int b    = blockIdx.x * WPB + wid;

    // Per-lane index/label staging (lanes < C / < K own one entry each)
    int   ctx_i = (lane < CC) ? contexts[b * CC + lane] : 0;
    int   foc_i = (lane < KK) ? focus[b * KK + lane]    : 0;
    float w     = (lane < KK) ? wmask [b * KK + lane]   : 0.0f;
    float y     = (lane < KK) ? labels[b * KK + lane]   : 0.0f;

    // ---- Enqueue all 18 row copies (16 B per lane, coalesced 512 B rows).
    // Lane l writes AND later reads byte range [16l,16l+16) of each row, so
    // per-thread cp.async.wait_group ordering is sufficient (no block sync).
#pragma unroll
    for (int c = 0; c < CC; ++c) {
        int row = __shfl_sync(0xffffffffu, ctx_i, c);
        cp16(&sbuf[wid][c][lane * 16],
             (const char*)&ctx_emb[(size_t)row * DIM] + lane * 16);
    }
#pragma unroll
    for (int k = 0; k < KK; ++k) {
        int row = __shfl_sync(0xffffffffu, foc_i, k);
        cp16(&sbuf[wid][CC + k][lane * 16],
             (const char*)&neg_emb[(size_t)row * DIM] + lane * 16);
    }
    asm volatile("cp.async.commit_group;\n" ::);
    asm volatile("cp.async.wait_group 0;\n" ::);
    __syncwarp();

    // ---- Sum-pool context embedding (lane owns dims [4l..4l+3]) ----
    float4 src = ((const float4*)sbuf[wid][0])[lane];
#pragma unroll
    for (int c = 1; c < CC; ++c) {
        float4 v = ((const float4*)sbuf[wid][c])[lane];
        src.x += v.x; src.y += v.y; src.z += v.z; src.w += v.w;
    }

    // ---- K dot products; butterfly reduce ----
    float pred_mine = 0.0f;
#pragma unroll
    for (int k = 0; k < KK; ++k) {
        float4 t = ((const float4*)sbuf[wid][CC + k])[lane];
        float d = src.x * t.x + src.y * t.y + src.z * t.z + src.w * t.w;
        d += __shfl_xor_sync(0xffffffffu, d, 16);
        d += __shfl_xor_sync(0xffffffffu, d, 8);
        d += __shfl_xor_sync(0xffffffffu, d, 4);
        d += __shfl_xor_sync(0xffffffffu, d, 2);
        d += __shfl_xor_sync(0xffffffffu, d, 1);
        if (lane == k) pred_mine = d;
    }

    // Lane k (< K) computes its weighted BCE term once
    float bce = 0.0f;
    if (lane < KK) {
        // logaddexp(0, x) = max(x,0) + log1p(exp(-|x|))  (stable softplus)
        float sp = fmaxf(pred_mine, 0.0f) + log1pf(expf(-fabsf(pred_mine)));
        bce = w * (sp - pred_mine * y);
    }

    // num = sum_k bce, den = sum_k w  (w is 0 on lanes >= K)
    float num = bce, den = w;
#pragma unroll
    for (int o = 16; o > 0; o >>= 1) {
        num += __shfl_xor_sync(0xffffffffu, num, o);
        den += __shfl_xor_sync(0xffffffffu, den, o);
    }

    // Per-warp row loss -> per-block partial (fixed order => deterministic)
    if (lane == 0) s_row[wid] = num / den;
    __syncthreads();
    if (threadIdx.x == 0)
        g_part[blockIdx.x] = (s_row[0] + s_row[1]) + (s_row[2] + s_row[3]);
}

// Stage 2a: 32 blocks x 128 threads, each reduces 128 partials
__global__ void __launch_bounds__(128) cbow_reduce1()
{
    __shared__ float s_acc[4];
    const int tid  = threadIdx.x;
    const int lane = tid & 31;
    const int warp = tid >> 5;

    float v = g_part[blockIdx.x * 128 + tid];
#pragma unroll
    for (int o = 16; o > 0; o >>= 1)
        v += __shfl_xor_sync(0xffffffffu, v, o);
    if (lane == 0) s_acc[warp] = v;
    __syncthreads();

    if (tid == 0)
        g_p2[blockIdx.x] = (double)((s_acc[0] + s_acc[1]) + (s_acc[2] + s_acc[3]));
}

// Stage 2b: one warp finishes 32 partials -> scalar mean
__global__ void __launch_bounds__(32) cbow_reduce2(float* __restrict__ out)
{
    const int lane = threadIdx.x;
    double v = g_p2[lane];
#pragma unroll
    for (int o = 16; o > 0; o >>= 1)
        v += __shfl_xor_sync(0xffffffffu, v, o);
    if (lane == 0) out[0] = (float)(v / (double)BB);
}

extern "C" void kernel_launch(void* const* d_in, const int* in_sizes, int n_in,
                              void* d_out, int out_size)
{
    const int*   contexts = (const int*)  d_in[0];   // [B, C] int32
    const int*   focus    = (const int*)  d_in[1];   // [B, K] int32
    const float* wmask    = (const float*)d_in[2];   // [B, K] f32
    const float* labels   = (const float*)d_in[3];   // [B, K] f32
    const float* ctx_emb  = (const float*)d_in[4];   // [VOCAB, DIM] f32
    const float* neg_emb  = (const float*)d_in[5];   // [VOCAB, DIM] f32
    float* out = (float*)d_out;

    cbow_main<<<NBLK, 32 * WPB>>>(contexts, focus, wmask, labels, ctx_emb, neg_emb);
    cbow_reduce1<<<NP2, 128>>>();
    cbow_reduce2<<<1, 32>>>(out);
}